// round 5
// baseline (speedup 1.0000x reference)
#include <cuda_runtime.h>
#include <math.h>

// ---------------------------------------------------------------------------
// 256-bit global ops with L2 policy (ptxas requires .v8.b32 with L2::evict_*).
// Input (96MB, re-read each graph replay, fits 126MB L2) -> evict_last
// (measured 43% read-hit in R3). Output (write-once) -> evict_first.
// ---------------------------------------------------------------------------
struct V8 { unsigned r0, r1, r2, r3, r4, r5, r6, r7; };

__device__ __forceinline__ V8 ldg256_el(const void* p) {
    V8 v;
    asm volatile("ld.global.nc.L2::evict_last.v8.b32 "
                 "{%0,%1,%2,%3,%4,%5,%6,%7}, [%8];"
                 : "=r"(v.r0), "=r"(v.r1), "=r"(v.r2), "=r"(v.r3),
                   "=r"(v.r4), "=r"(v.r5), "=r"(v.r6), "=r"(v.r7)
                 : "l"(p));
    return v;
}
__device__ __forceinline__ void stg256_ef(void* p, const float* g) {
    asm volatile("st.global.L2::evict_first.v8.b32 "
                 "[%0], {%1,%2,%3,%4,%5,%6,%7,%8};"
                 :: "l"(p),
                    "r"(__float_as_uint(g[0])), "r"(__float_as_uint(g[1])),
                    "r"(__float_as_uint(g[2])), "r"(__float_as_uint(g[3])),
                    "r"(__float_as_uint(g[4])), "r"(__float_as_uint(g[5])),
                    "r"(__float_as_uint(g[6])), "r"(__float_as_uint(g[7]))
                 : "memory");
}

__device__ __forceinline__ void unpack8(const V8& v, float* f) {
    f[0] = __uint_as_float(v.r0); f[1] = __uint_as_float(v.r1);
    f[2] = __uint_as_float(v.r2); f[3] = __uint_as_float(v.r3);
    f[4] = __uint_as_float(v.r4); f[5] = __uint_as_float(v.r5);
    f[6] = __uint_as_float(v.r6); f[7] = __uint_as_float(v.r7);
}

// ---------------------------------------------------------------------------
// Fused kernel, 16 points per thread: 6 front-batched 256-bit loads (MLP=6,
// 2KB outstanding reads per warp) then FMA + 6 stores. Thread 0 of each block
// computes the SE(3) exp map (fp32; contributes ~1e-6 of the 1e-3 budget)
// and broadcasts R|t via smem. No min-blocks occupancy cap: registers are
// allowed to grow so all 6 loads stay simultaneously in flight.
// ---------------------------------------------------------------------------
__global__ void __launch_bounds__(256)
se3_kernel16(const float* __restrict__ pose,
             const char* __restrict__ xb, char* __restrict__ ob,
             int n_hex,
             const float* __restrict__ x_tail, float* __restrict__ o_tail,
             int n_tail) {
    __shared__ float sRt[12];

    if (threadIdx.x == 0) {
        float tx = pose[0], ty = pose[1], tz = pose[2];
        float px = pose[3], py = pose[4], pz = pose[5];
        float th2 = px * px + py * py + pz * pz;
        float A, B, C;
        if (th2 < 1e-8f) {
            A = 1.0f - th2 / 6.0f;
            B = 0.5f - th2 / 24.0f;
            C = 1.0f / 6.0f - th2 / 120.0f;
        } else {
            float th = sqrtf(th2);
            float s = sinf(th), c = cosf(th);
            A = s / th;
            B = (1.0f - c) / th2;
            C = (th - s) / (th2 * th);
        }
        // Phi^2 = phi*phi^T - th2*I (skew-symmetric identity)
        sRt[0] = 1.0f + B * (px * px - th2);
        sRt[1] = -A * pz + B * px * py;
        sRt[2] =  A * py + B * px * pz;
        sRt[3] =  A * pz + B * px * py;
        sRt[4] = 1.0f + B * (py * py - th2);
        sRt[5] = -A * px + B * py * pz;
        sRt[6] = -A * py + B * px * pz;
        sRt[7] =  A * px + B * py * pz;
        sRt[8] = 1.0f + B * (pz * pz - th2);

        float V0 = 1.0f + C * (px * px - th2);
        float V1 = -B * pz + C * px * py;
        float V2 =  B * py + C * px * pz;
        float V3 =  B * pz + C * px * py;
        float V4 = 1.0f + C * (py * py - th2);
        float V5 = -B * px + C * py * pz;
        float V6 = -B * py + C * px * pz;
        float V7 =  B * px + C * py * pz;
        float V8v = 1.0f + C * (pz * pz - th2);

        sRt[9]  = V0 * tx + V1 * ty + V2 * tz;
        sRt[10] = V3 * tx + V4 * ty + V5 * tz;
        sRt[11] = V6 * tx + V7 * ty + V8v * tz;
    }
    __syncthreads();

    float Rt[12];
    #pragma unroll
    for (int k = 0; k < 12; k++) Rt[k] = sRt[k];

    int i = blockIdx.x * blockDim.x + threadIdx.x;

    if (i < n_hex) {
        const char* p = xb + (size_t)192 * i;
        // Front-batch all 6 x 256-bit loads: MLP = 6 per thread.
        V8 v0 = ldg256_el(p);
        V8 v1 = ldg256_el(p + 32);
        V8 v2 = ldg256_el(p + 64);
        V8 v3 = ldg256_el(p + 96);
        V8 v4 = ldg256_el(p + 128);
        V8 v5 = ldg256_el(p + 160);

        float f[48];
        unpack8(v0, f);      unpack8(v1, f + 8);  unpack8(v2, f + 16);
        unpack8(v3, f + 24); unpack8(v4, f + 32); unpack8(v5, f + 40);

        float g[48];
        #pragma unroll
        for (int k = 0; k < 16; k++) {
            float X = f[3 * k], Y = f[3 * k + 1], Z = f[3 * k + 2];
            g[3 * k + 0] = fmaf(Rt[0], X, fmaf(Rt[1], Y, fmaf(Rt[2], Z, Rt[9])));
            g[3 * k + 1] = fmaf(Rt[3], X, fmaf(Rt[4], Y, fmaf(Rt[5], Z, Rt[10])));
            g[3 * k + 2] = fmaf(Rt[6], X, fmaf(Rt[7], Y, fmaf(Rt[8], Z, Rt[11])));
        }

        char* q = ob + (size_t)192 * i;
        stg256_ef(q,       g);
        stg256_ef(q + 32,  g + 8);
        stg256_ef(q + 64,  g + 16);
        stg256_ef(q + 96,  g + 24);
        stg256_ef(q + 128, g + 32);
        stg256_ef(q + 160, g + 40);
    } else if (i == n_hex && n_tail > 0) {
        // Scalar tail (N % 16 points); dead for N = 8388608 but general.
        for (int k = 0; k < n_tail; k++) {
            int base = (n_hex * 16 + k) * 3;
            float X = x_tail[base + 0], Y = x_tail[base + 1],
                  Z = x_tail[base + 2];
            o_tail[base + 0] = fmaf(Rt[0], X, fmaf(Rt[1], Y, fmaf(Rt[2], Z, Rt[9])));
            o_tail[base + 1] = fmaf(Rt[3], X, fmaf(Rt[4], Y, fmaf(Rt[5], Z, Rt[10])));
            o_tail[base + 2] = fmaf(Rt[6], X, fmaf(Rt[7], Y, fmaf(Rt[8], Z, Rt[11])));
        }
    }
}

// ---------------------------------------------------------------------------
// Launch: flat grid (wave count proved irrelevant in R4).
// ---------------------------------------------------------------------------
extern "C" void kernel_launch(void* const* d_in, const int* in_sizes, int n_in,
                              void* d_out, int out_size) {
    const float* pose = (const float*)d_in[0];  // (1, 6)
    const float* x    = (const float*)d_in[1];  // (N, 3)
    float* out = (float*)d_out;

    int n_points = in_sizes[1] / 3;
    int n_hex    = n_points / 16;
    int n_tail   = n_points % 16;

    const int threads = 256;
    int blocks = (n_hex + 1 + threads - 1) / threads;  // +1 thread for tail

    se3_kernel16<<<blocks, threads>>>(
        pose, (const char*)x, (char*)out, n_hex, x, out, n_tail);
}

// round 6
// speedup vs baseline: 1.2700x; 1.2700x over previous
#include <cuda_runtime.h>
#include <math.h>
#include <stdint.h>

// ---------------------------------------------------------------------------
// TMA-streamed SE(3) transform.
// Rationale (R5 post-mortem): per-SM L1tex wavefront queue caps LDG/STG
// streaming at ~4.7TB/s. cp.async.bulk moves bytes GMEM<->SMEM through the
// TMA engine + L2, bypassing that queue.
// ---------------------------------------------------------------------------

#define CHUNK_BYTES   24576            // 2048 points * 12B; 16B-aligned
#define CHUNK_POINTS  2048
#define NTHREADS      256
#define BYTES_PER_THR 96               // 8 points per thread per chunk

// Dynamic smem layout: IN[2] | OUT[2] | mbarriers(2)
#define SMEM_IN(s)   ((s) * CHUNK_BYTES)
#define SMEM_OUT(s)  (2 * CHUNK_BYTES + (s) * CHUNK_BYTES)
#define SMEM_MBAR    (4 * CHUNK_BYTES)
#define SMEM_TOTAL   (4 * CHUNK_BYTES + 64)

__device__ __forceinline__ uint32_t smem_u32(const void* p) {
    uint32_t a;
    asm("{ .reg .u64 t; cvta.to.shared.u64 t, %1; cvt.u32.u64 %0, t; }"
        : "=r"(a) : "l"(p));
    return a;
}

__device__ __forceinline__ void mbar_init(uint32_t mbar, uint32_t count) {
    asm volatile("mbarrier.init.shared.b64 [%0], %1;" :: "r"(mbar), "r"(count)
                 : "memory");
}
__device__ __forceinline__ void mbar_expect_tx(uint32_t mbar, uint32_t bytes) {
    asm volatile("mbarrier.arrive.expect_tx.shared.b64 _, [%0], %1;"
                 :: "r"(mbar), "r"(bytes) : "memory");
}
__device__ __forceinline__ void mbar_wait(uint32_t mbar, uint32_t parity) {
    asm volatile(
        "{\n\t"
        ".reg .pred P;\n\t"
        "LAB_WAIT_%=:\n\t"
        "mbarrier.try_wait.parity.acquire.cta.shared::cta.b64 P, [%0], %1, 0x989680;\n\t"
        "@P bra LAB_DONE_%=;\n\t"
        "bra LAB_WAIT_%=;\n\t"
        "LAB_DONE_%=:\n\t"
        "}"
        :: "r"(mbar), "r"(parity) : "memory");
}

__device__ __forceinline__ void bulk_ld(uint32_t dst_smem, const char* src,
                                        uint32_t mbar, uint64_t pol) {
    asm volatile(
        "cp.async.bulk.shared::cluster.global.mbarrier::complete_tx::bytes"
        ".L2::cache_hint [%0], [%1], %2, [%3], %4;"
        :: "r"(dst_smem), "l"(src), "r"((uint32_t)CHUNK_BYTES), "r"(mbar),
           "l"(pol)
        : "memory");
}
__device__ __forceinline__ void bulk_st(char* dst, uint32_t src_smem,
                                        uint64_t pol) {
    asm volatile(
        "cp.async.bulk.global.shared::cta.bulk_group.L2::cache_hint"
        " [%0], [%1], %2, %3;"
        :: "l"(dst), "r"(src_smem), "r"((uint32_t)CHUNK_BYTES), "l"(pol)
        : "memory");
}

__global__ void __launch_bounds__(NTHREADS)
se3_tma_kernel(const float* __restrict__ pose,
               const char* __restrict__ xb, char* __restrict__ ob,
               int n_chunks, int n_points) {
    extern __shared__ char smem[];
    __shared__ float sRt[12];
    const int tid = threadIdx.x;

    // --- SE(3) exp map (thread 0; fp32 is ~1e-6 of the 1e-3 budget) ---
    if (tid == 0) {
        float tx = pose[0], ty = pose[1], tz = pose[2];
        float px = pose[3], py = pose[4], pz = pose[5];
        float th2 = px * px + py * py + pz * pz;
        float A, B, C;
        if (th2 < 1e-8f) {
            A = 1.0f - th2 / 6.0f;
            B = 0.5f - th2 / 24.0f;
            C = 1.0f / 6.0f - th2 / 120.0f;
        } else {
            float th = sqrtf(th2);
            float s = sinf(th), c = cosf(th);
            A = s / th;
            B = (1.0f - c) / th2;
            C = (th - s) / (th2 * th);
        }
        sRt[0] = 1.0f + B * (px * px - th2);
        sRt[1] = -A * pz + B * px * py;
        sRt[2] =  A * py + B * px * pz;
        sRt[3] =  A * pz + B * px * py;
        sRt[4] = 1.0f + B * (py * py - th2);
        sRt[5] = -A * px + B * py * pz;
        sRt[6] = -A * py + B * px * pz;
        sRt[7] =  A * px + B * py * pz;
        sRt[8] = 1.0f + B * (pz * pz - th2);
        float V0 = 1.0f + C * (px * px - th2);
        float V1 = -B * pz + C * px * py;
        float V2 =  B * py + C * px * pz;
        float V3 =  B * pz + C * px * py;
        float V4 = 1.0f + C * (py * py - th2);
        float V5 = -B * px + C * py * pz;
        float V6 = -B * py + C * px * pz;
        float V7 =  B * px + C * py * pz;
        float V8 = 1.0f + C * (pz * pz - th2);
        sRt[9]  = V0 * tx + V1 * ty + V2 * tz;
        sRt[10] = V3 * tx + V4 * ty + V5 * tz;
        sRt[11] = V6 * tx + V7 * ty + V8 * tz;
    }

    const uint32_t sbase = smem_u32(smem);
    const uint32_t mbar0 = sbase + SMEM_MBAR;
    const uint32_t mbar1 = sbase + SMEM_MBAR + 8;

    if (tid == 0) {
        mbar_init(mbar0, 1);
        mbar_init(mbar1, 1);
    }
    __syncthreads();

    float Rt[12];
    #pragma unroll
    for (int k = 0; k < 12; k++) Rt[k] = sRt[k];

    uint64_t pol_ld, pol_st;
    asm("createpolicy.fractional.L2::evict_last.b64 %0, 1.0;" : "=l"(pol_ld));
    asm("createpolicy.fractional.L2::evict_first.b64 %0, 1.0;" : "=l"(pol_st));

    // --- double-buffered TMA streaming over grid-strided chunks ---
    int phase0 = 0, phase1 = 0;
    const int c0 = blockIdx.x;
    if (c0 < n_chunks && tid == 0) {
        mbar_expect_tx(mbar0, CHUNK_BYTES);
        bulk_ld(sbase + SMEM_IN(0), xb + (size_t)c0 * CHUNK_BYTES, mbar0, pol_ld);
    }

    int j = 0;
    for (int c = c0; c < n_chunks; c += gridDim.x, j++) {
        const int s = j & 1;
        // Prefetch next chunk into the other IN slot (consumed 1 iter ago).
        const int cn = c + gridDim.x;
        if (cn < n_chunks && tid == 0) {
            const uint32_t mb = (s == 0) ? mbar1 : mbar0;
            mbar_expect_tx(mb, CHUNK_BYTES);
            bulk_ld(sbase + SMEM_IN(s ^ 1), xb + (size_t)cn * CHUNK_BYTES, mb,
                    pol_ld);
        }
        // Wait current chunk's data.
        if (s == 0) { mbar_wait(mbar0, phase0); phase0 ^= 1; }
        else        { mbar_wait(mbar1, phase1); phase1 ^= 1; }

        // Transform 8 points from smem IN -> smem OUT.
        {
            const char* inb = smem + SMEM_IN(s)  + tid * BYTES_PER_THR;
            char*       otb = smem + SMEM_OUT(s) + tid * BYTES_PER_THR;
            float4 a = ((const float4*)inb)[0];
            float4 b = ((const float4*)inb)[1];
            float4 cc = ((const float4*)inb)[2];
            float4 d = ((const float4*)inb)[3];
            float4 e = ((const float4*)inb)[4];
            float4 h = ((const float4*)inb)[5];
            float f[24] = { a.x, a.y, a.z, a.w,  b.x, b.y, b.z, b.w,
                            cc.x, cc.y, cc.z, cc.w,  d.x, d.y, d.z, d.w,
                            e.x, e.y, e.z, e.w,  h.x, h.y, h.z, h.w };
            float g[24];
            #pragma unroll
            for (int k = 0; k < 8; k++) {
                float X = f[3 * k], Y = f[3 * k + 1], Z = f[3 * k + 2];
                g[3*k+0] = fmaf(Rt[0], X, fmaf(Rt[1], Y, fmaf(Rt[2], Z, Rt[9])));
                g[3*k+1] = fmaf(Rt[3], X, fmaf(Rt[4], Y, fmaf(Rt[5], Z, Rt[10])));
                g[3*k+2] = fmaf(Rt[6], X, fmaf(Rt[7], Y, fmaf(Rt[8], Z, Rt[11])));
            }
            ((float4*)otb)[0] = make_float4(g[0],  g[1],  g[2],  g[3]);
            ((float4*)otb)[1] = make_float4(g[4],  g[5],  g[6],  g[7]);
            ((float4*)otb)[2] = make_float4(g[8],  g[9],  g[10], g[11]);
            ((float4*)otb)[3] = make_float4(g[12], g[13], g[14], g[15]);
            ((float4*)otb)[4] = make_float4(g[16], g[17], g[18], g[19]);
            ((float4*)otb)[5] = make_float4(g[20], g[21], g[22], g[23]);
        }
        __syncthreads();  // OUT fully written; IN fully consumed

        if (tid == 0) {
            asm volatile("fence.proxy.async.shared::cta;" ::: "memory");
            bulk_st(ob + (size_t)c * CHUNK_BYTES, sbase + SMEM_OUT(s), pol_st);
            asm volatile("cp.async.bulk.commit_group;" ::: "memory");
            // <=1 group pending reads -> OUT slot from 2 iters ago reusable.
            asm volatile("cp.async.bulk.wait_group.read 1;" ::: "memory");
        }
        __syncthreads();  // all threads see OUT-reuse clearance
    }

    if (tid == 0)
        asm volatile("cp.async.bulk.wait_group.read 0;" ::: "memory");

    // --- tail points not covered by whole chunks (zero for N=8388608) ---
    const int tail_start = n_chunks * CHUNK_POINTS;
    for (int p = tail_start + blockIdx.x * blockDim.x + tid; p < n_points;
         p += gridDim.x * blockDim.x) {
        const float* xi = (const float*)xb + (size_t)3 * p;
        float*       oi = (float*)ob + (size_t)3 * p;
        float X = xi[0], Y = xi[1], Z = xi[2];
        oi[0] = fmaf(Rt[0], X, fmaf(Rt[1], Y, fmaf(Rt[2], Z, Rt[9])));
        oi[1] = fmaf(Rt[3], X, fmaf(Rt[4], Y, fmaf(Rt[5], Z, Rt[10])));
        oi[2] = fmaf(Rt[6], X, fmaf(Rt[7], Y, fmaf(Rt[8], Z, Rt[11])));
    }
}

// ---------------------------------------------------------------------------
extern "C" void kernel_launch(void* const* d_in, const int* in_sizes, int n_in,
                              void* d_out, int out_size) {
    const float* pose = (const float*)d_in[0];  // (1, 6)
    const char*  x    = (const char*)d_in[1];   // (N, 3) fp32
    char* out = (char*)d_out;

    int n_points = in_sizes[1] / 3;
    int n_chunks = n_points / CHUNK_POINTS;

    cudaFuncSetAttribute(se3_tma_kernel,
                         cudaFuncAttributeMaxDynamicSharedMemorySize,
                         SMEM_TOTAL);

    int blocks = 148 * 2;                 // 2 blocks/SM (96KB smem each)
    if (blocks > n_chunks && n_chunks > 0) blocks = n_chunks;
    if (n_chunks == 0) blocks = 1;

    se3_tma_kernel<<<blocks, NTHREADS, SMEM_TOTAL>>>(
        pose, x, out, n_chunks, n_points);
}